// round 5
// baseline (speedup 1.0000x reference)
#include <cuda_runtime.h>

#define N_NODES 100000
#define D_IN    2048
#define H_DIM   50
#define C_CLS   6
#define M_EDGES 3200000
#define L_LAYERS 3

// ---------------- scratch (device globals; no allocation allowed) ----------
__device__ __align__(16) float g_Vexp[M_EDGES];        // e^{-rel}, 12.8 MB
__device__ __align__(16) float g_x1[N_NODES * H_DIM];  // layer-1 activations, 20 MB
__device__ __align__(16) float g_z [N_NODES * 8];      // z padded to 8 floats/row (32B align for float4 atomics)
__device__ __align__(16) float g_Em[N_NODES * 8];      // e^{-z} table
__device__ __align__(16) float g_Ep[N_NODES * 8];      // e^{+z} table

typedef unsigned long long ull;

__device__ __forceinline__ ull pack2(float x, float y) {
    ull r; asm("mov.b64 %0, {%1, %2};" : "=l"(r) : "f"(x), "f"(y)); return r;
}
__device__ __forceinline__ void unpack2(ull v, float& x, float& y) {
    asm("mov.b64 {%0, %1}, %2;" : "=f"(x), "=f"(y) : "l"(v));
}
// Blackwell packed fp32 FMA (2x scalar FFMA throughput)
__device__ __forceinline__ ull ffma2(ull a, ull b, ull c) {
    ull d; asm("fma.rn.f32x2 %0, %1, %2, %3;" : "=l"(d) : "l"(a), "l"(b), "l"(c)); return d;
}
__device__ __forceinline__ float rcpa(float x) {
    float r; asm("rcp.approx.f32 %0, %1;" : "=f"(r) : "f"(x)); return r;
}

// ---------------- K0: v = exp(-rel) --------------------------------------
__global__ void vexp_kernel(const float* __restrict__ rel) {
    int m = blockIdx.x * 256 + threadIdx.x;
    if (m < M_EDGES) g_Vexp[m] = __expf(-rel[m]);
}

// ---------------- K1: x1 = relu(F @ W1 + b1) ------------------------------
// 256 threads/CTA, 256 nodes/CTA, each thread owns one node's 50 outputs
// as 25 f32x2 accumulators. K staged in chunks of 32.
__global__ __launch_bounds__(256) void gemm1_kernel(
    const float* __restrict__ F, const float* __restrict__ W1,
    const float* __restrict__ b1)
{
    __shared__ __align__(16) float sF[256 * 33];  // feature tile, pad 33 -> conflict-free
    __shared__ __align__(16) float sW[32 * 50];   // W1 k-chunk

    int tid  = threadIdx.x;
    int n0   = blockIdx.x * 256;
    int node = n0 + tid;
    int warp = tid >> 5, lane = tid & 31;

    ull acc[25];
#pragma unroll
    for (int j = 0; j < 25; j++) acc[j] = 0ull;

    for (int kc = 0; kc < D_IN; kc += 32) {
        // W1 chunk: rows kc..kc+31, flat & contiguous
        for (int i = tid; i < 32 * 50; i += 256) sW[i] = W1[kc * 50 + i];
        // feature tile: sF[i][k] = F[n0+i][kc+k], coalesced 128B rows
        for (int i = warp; i < 256; i += 8) {
            int n = n0 + i;
            float v = (n < N_NODES) ? F[(size_t)n * D_IN + kc + lane] : 0.f;
            sF[i * 33 + lane] = v;
        }
        __syncthreads();

        const float* fr = &sF[tid * 33];
#pragma unroll 8
        for (int k = 0; k < 32; k++) {
            float f = fr[k];
            ull f2 = pack2(f, f);
            const float* wr = &sW[k * 50];
#pragma unroll
            for (int j = 0; j < 25; j++)
                acc[j] = ffma2(f2, *(const ull*)(wr + 2 * j), acc[j]);  // broadcast LDS.64
        }
        __syncthreads();
    }

    if (node < N_NODES) {
        float* out = &g_x1[(size_t)node * H_DIM];
#pragma unroll
        for (int j = 0; j < 25; j++) {
            float a, b; unpack2(acc[j], a, b);
            a = fmaxf(a + b1[2 * j],     0.f);
            b = fmaxf(b + b1[2 * j + 1], 0.f);
            *(float2*)(out + 2 * j) = make_float2(a, b);
        }
    }
}

// ---------------- K2: fused layers 2..4 -> z ------------------------------
__global__ __launch_bounds__(128) void mlp_tail_kernel(
    const float* __restrict__ W2, const float* __restrict__ b2,
    const float* __restrict__ W3, const float* __restrict__ b3,
    const float* __restrict__ W4, const float* __restrict__ b4)
{
    __shared__ __align__(16) float sW2[2500];
    __shared__ __align__(16) float sW3[2500];
    __shared__ __align__(16) float sW4[304];
    __shared__ float sB2[56], sB3[56], sB4[8];

    int tid = threadIdx.x;
    for (int i = tid; i < 2500; i += 128) { sW2[i] = W2[i]; sW3[i] = W3[i]; }
    for (int i = tid; i < 300;  i += 128) sW4[i] = W4[i];
    if (tid < 50) { sB2[tid] = b2[tid]; sB3[tid] = b3[tid]; }
    if (tid < 6)  sB4[tid] = b4[tid];
    __syncthreads();

    int node = blockIdx.x * 128 + tid;
    if (node >= N_NODES) return;

    float xa[50];
    const float* xin = &g_x1[(size_t)node * H_DIM];
#pragma unroll
    for (int j = 0; j < 25; j++) {
        float2 v = *(const float2*)(xin + 2 * j);
        xa[2 * j] = v.x; xa[2 * j + 1] = v.y;
    }

    // layer 2
    {
        ull acc[25];
#pragma unroll
        for (int j = 0; j < 25; j++) acc[j] = 0ull;
#pragma unroll
        for (int k = 0; k < 50; k++) {
            ull f2 = pack2(xa[k], xa[k]);
            const float* wr = &sW2[k * 50];
#pragma unroll
            for (int j = 0; j < 25; j++)
                acc[j] = ffma2(f2, *(const ull*)(wr + 2 * j), acc[j]);
        }
#pragma unroll
        for (int j = 0; j < 25; j++) {
            float a, b; unpack2(acc[j], a, b);
            xa[2 * j]     = fmaxf(a + sB2[2 * j],     0.f);
            xa[2 * j + 1] = fmaxf(b + sB2[2 * j + 1], 0.f);
        }
    }
    // layer 3
    {
        ull acc[25];
#pragma unroll
        for (int j = 0; j < 25; j++) acc[j] = 0ull;
#pragma unroll
        for (int k = 0; k < 50; k++) {
            ull f2 = pack2(xa[k], xa[k]);
            const float* wr = &sW3[k * 50];
#pragma unroll
            for (int j = 0; j < 25; j++)
                acc[j] = ffma2(f2, *(const ull*)(wr + 2 * j), acc[j]);
        }
#pragma unroll
        for (int j = 0; j < 25; j++) {
            float a, b; unpack2(acc[j], a, b);
            xa[2 * j]     = fmaxf(a + sB3[2 * j],     0.f);
            xa[2 * j + 1] = fmaxf(b + sB3[2 * j + 1], 0.f);
        }
    }
    // layer 4 -> z (padded row of 8)
    {
        ull acc[3] = {0ull, 0ull, 0ull};
#pragma unroll
        for (int k = 0; k < 50; k++) {
            ull f2 = pack2(xa[k], xa[k]);
            const float* wr = &sW4[k * 6];
#pragma unroll
            for (int j = 0; j < 3; j++)
                acc[j] = ffma2(f2, *(const ull*)(wr + 2 * j), acc[j]);
        }
        float zr[6];
#pragma unroll
        for (int j = 0; j < 3; j++) {
            float a, b; unpack2(acc[j], a, b);
            zr[2 * j]     = a + sB4[2 * j];
            zr[2 * j + 1] = b + sB4[2 * j + 1];
        }
        float* zp = &g_z[(size_t)node * 8];
        *(float4*)zp       = make_float4(zr[0], zr[1], zr[2], zr[3]);
        *(float2*)(zp + 4) = make_float2(zr[4], zr[5]);
        *(float2*)(zp + 6) = make_float2(0.f, 0.f);
    }
}

// ---------------- K3: per-layer exp tables --------------------------------
__global__ void table_kernel() {
    int n = blockIdx.x * 256 + threadIdx.x;
    if (n >= N_NODES) return;
    const float* zp = &g_z[(size_t)n * 8];
    float4 z4 = *(const float4*)zp;
    float2 z2 = *(const float2*)(zp + 4);
    float zz[6] = {z4.x, z4.y, z4.z, z4.w, z2.x, z2.y};
    float em[6], ep[6];
#pragma unroll
    for (int c = 0; c < 6; c++) { ep[c] = __expf(zz[c]); em[c] = __expf(-zz[c]); }
    float* e1 = &g_Em[(size_t)n * 8];
    float* e2 = &g_Ep[(size_t)n * 8];
    *(float4*)e1       = make_float4(em[0], em[1], em[2], em[3]);
    *(float2*)(e1 + 4) = make_float2(em[4], em[5]);
    *(float4*)e2       = make_float4(ep[0], ep[1], ep[2], ep[3]);
    *(float2*)(e2 + 4) = make_float2(ep[4], ep[5]);
}

// ---------------- K4: edge enhancement (scatter directly into z) ----------
__global__ __launch_bounds__(256) void edge_kernel(
    const int* __restrict__ sx, const int* __restrict__ sy,
    const float* __restrict__ cw)   // clause_weights + 6*layer
{
    int m = blockIdx.x * 256 + threadIdx.x;
    if (m >= M_EDGES) return;
    int a = sx[m], b = sy[m];
    float v = g_Vexp[m];

    const float* ue = &g_Em[(size_t)a * 8];
    const float* we = &g_Ep[(size_t)b * 8];
    float4 u4 = *(const float4*)ue;  float2 u2 = *(const float2*)(ue + 4);
    float4 w4 = *(const float4*)we;  float2 w2 = *(const float2*)(we + 4);
    float u[6] = {u4.x, u4.y, u4.z, u4.w, u2.x, u2.y};
    float w[6] = {w4.x, w4.y, w4.z, w4.w, w2.x, w2.y};

    float dx[6], dy[6];
#pragma unroll
    for (int c = 0; c < 6; c++) {
        float S   = u[c] + v + w[c];
        float inv = rcpa(S);
        float t   = __ldg(&cw[c]) * inv;
        dx[c] = -t * u[c];   // sign -1 literal at sx
        dy[c] =  t * w[c];   // sign +1 literal at sy
    }
    float* za = &g_z[(size_t)a * 8];
    float* zb = &g_z[(size_t)b * 8];
    atomicAdd((float4*)za,       make_float4(dx[0], dx[1], dx[2], dx[3]));
    atomicAdd((float2*)(za + 4), make_float2(dx[4], dx[5]));
    atomicAdd((float4*)zb,       make_float4(dy[0], dy[1], dy[2], dy[3]));
    atomicAdd((float2*)(zb + 4), make_float2(dy[4], dy[5]));
}

// ---------------- K5: final softmax -> d_out ------------------------------
__global__ void softmax_kernel(float* __restrict__ out) {
    int n = blockIdx.x * 256 + threadIdx.x;
    if (n >= N_NODES) return;
    const float* zp = &g_z[(size_t)n * 8];
    float4 z4 = *(const float4*)zp;
    float2 z2 = *(const float2*)(zp + 4);
    float zz[6] = {z4.x, z4.y, z4.z, z4.w, z2.x, z2.y};
    float mx = zz[0];
#pragma unroll
    for (int c = 1; c < 6; c++) mx = fmaxf(mx, zz[c]);
    float e[6], s = 0.f;
#pragma unroll
    for (int c = 0; c < 6; c++) { e[c] = __expf(zz[c] - mx); s += e[c]; }
    float inv = rcpa(s);
    float* op = out + (size_t)n * 6;
#pragma unroll
    for (int c = 0; c < 6; c++) op[c] = e[c] * inv;
}

// ---------------- launcher ------------------------------------------------
extern "C" void kernel_launch(void* const* d_in, const int* in_sizes, int n_in,
                              void* d_out, int out_size)
{
    const float* F   = (const float*)d_in[0];
    const float* rel = (const float*)d_in[1];
    const int*   sx  = (const int*)d_in[2];
    const int*   sy  = (const int*)d_in[3];
    const float* W1  = (const float*)d_in[4];
    const float* b1  = (const float*)d_in[5];
    const float* W2  = (const float*)d_in[6];
    const float* b2  = (const float*)d_in[7];
    const float* W3  = (const float*)d_in[8];
    const float* b3  = (const float*)d_in[9];
    const float* W4  = (const float*)d_in[10];
    const float* b4  = (const float*)d_in[11];
    const float* cw  = (const float*)d_in[12];
    float* out = (float*)d_out;

    vexp_kernel   <<<(M_EDGES + 255) / 256, 256>>>(rel);
    gemm1_kernel  <<<(N_NODES + 255) / 256, 256>>>(F, W1, b1);
    mlp_tail_kernel<<<(N_NODES + 127) / 128, 128>>>(W2, b2, W3, b3, W4, b4);

    for (int l = 0; l < L_LAYERS; l++) {
        table_kernel<<<(N_NODES + 255) / 256, 256>>>();
        edge_kernel <<<(M_EDGES + 255) / 256, 256>>>(sx, sy, cw + l * 6);
    }
    softmax_kernel<<<(N_NODES + 255) / 256, 256>>>(out);
}

// round 6
// speedup vs baseline: 1.5177x; 1.5177x over previous
#include <cuda_runtime.h>

#define N_NODES 100000
#define D_IN    2048
#define H_DIM   50
#define C_CLS   6
#define M_EDGES 3200000
#define L_LAYERS 3

// ---------------- scratch (device globals; no allocation allowed) ----------
__device__ __align__(16) float g_Vexp[M_EDGES];        // e^{-rel}
__device__ __align__(16) float g_x1[N_NODES * H_DIM];  // layer-1 activations
__device__ __align__(16) float g_z [N_NODES * 8];      // z padded to 8 floats/row
__device__ __align__(16) float g_Em[N_NODES * 8];      // e^{-z} (pads [6,7] stay 0)
__device__ __align__(16) float g_Ep[N_NODES * 8];      // e^{+z} (pads [6,7] stay 0)

typedef unsigned long long ull;

__device__ __forceinline__ ull pack2(float x, float y) {
    ull r; asm("mov.b64 %0, {%1, %2};" : "=l"(r) : "f"(x), "f"(y)); return r;
}
__device__ __forceinline__ void unpack2(ull v, float& x, float& y) {
    asm("mov.b64 {%0, %1}, %2;" : "=f"(x), "=f"(y) : "l"(v));
}
// Blackwell packed fp32 FMA (2x scalar FFMA throughput)
__device__ __forceinline__ ull ffma2(ull a, ull b, ull c) {
    ull d; asm("fma.rn.f32x2 %0, %1, %2, %3;" : "=l"(d) : "l"(a), "l"(b), "l"(c)); return d;
}
__device__ __forceinline__ float rcpa(float x) {
    float r; asm("rcp.approx.f32 %0, %1;" : "=f"(r) : "f"(x)); return r;
}

// ---------------- nop: shifts ncu capture slot onto edge_kernel -----------
__global__ void nop_kernel() {}

// ---------------- K0: v = exp(-rel) --------------------------------------
__global__ void vexp_kernel(const float* __restrict__ rel) {
    int m = blockIdx.x * 256 + threadIdx.x;
    if (m < M_EDGES) g_Vexp[m] = __expf(-rel[m]);
}

// ---------------- K1: x1 = relu(F @ W1 + b1) ------------------------------
// 128 threads/CTA, 256 nodes/CTA (2 nodes/thread: tid and tid+128).
// Weights read via LDS.128 (padded stride 52), shared across both nodes:
// 15 LDS per 50 FFMA2 -> fma-pipe-bound instead of LDS-bound.
__global__ __launch_bounds__(128) void gemm1_kernel(
    const float* __restrict__ F, const float* __restrict__ W1,
    const float* __restrict__ b1)
{
    __shared__ __align__(16) float sF[256 * 33];  // stride 33 -> conflict-free scalar reads
    __shared__ __align__(16) float sW[32 * 52];   // stride 52 -> 16B-aligned rows

    int tid  = threadIdx.x;
    int n0   = blockIdx.x * 256;
    int warp = tid >> 5, lane = tid & 31;
    int nodeA = n0 + tid;
    int nodeB = n0 + 128 + tid;

    ull accA[25], accB[25];
#pragma unroll
    for (int j = 0; j < 25; j++) { accA[j] = 0ull; accB[j] = 0ull; }

    for (int kc = 0; kc < D_IN; kc += 32) {
        // stage W1 chunk (32 rows x 50 cols) into padded stride-52 layout
        for (int i = tid; i < 32 * 50; i += 128) {
            int r = i / 50, c = i - r * 50;
            sW[r * 52 + c] = W1[(kc + r) * 50 + c];
        }
        // stage feature tile: 256 rows x 32 cols, one 128B row per warp-iter
        for (int i = warp; i < 256; i += 4) {
            int n = n0 + i;
            sF[i * 33 + lane] = (n < N_NODES) ? F[(size_t)n * D_IN + kc + lane] : 0.f;
        }
        __syncthreads();

        const float* frA = &sF[tid * 33];
        const float* frB = &sF[(tid + 128) * 33];
#pragma unroll 8
        for (int k = 0; k < 32; k++) {
            float fa = frA[k], fb = frB[k];
            ull fa2 = pack2(fa, fa);
            ull fb2 = pack2(fb, fb);
            const ull* wr = (const ull*)&sW[k * 52];
#pragma unroll
            for (int j = 0; j < 12; j++) {
                ulonglong2 w2 = *(const ulonglong2*)(wr + 2 * j);   // LDS.128 broadcast
                accA[2 * j]     = ffma2(fa2, w2.x, accA[2 * j]);
                accA[2 * j + 1] = ffma2(fa2, w2.y, accA[2 * j + 1]);
                accB[2 * j]     = ffma2(fb2, w2.x, accB[2 * j]);
                accB[2 * j + 1] = ffma2(fb2, w2.y, accB[2 * j + 1]);
            }
            ull wl = wr[24];                                        // LDS.64 broadcast
            accA[24] = ffma2(fa2, wl, accA[24]);
            accB[24] = ffma2(fb2, wl, accB[24]);
        }
        __syncthreads();
    }

    if (nodeA < N_NODES) {
        float* out = &g_x1[(size_t)nodeA * H_DIM];
#pragma unroll
        for (int j = 0; j < 25; j++) {
            float a, b; unpack2(accA[j], a, b);
            a = fmaxf(a + __ldg(&b1[2 * j]),     0.f);
            b = fmaxf(b + __ldg(&b1[2 * j + 1]), 0.f);
            *(float2*)(out + 2 * j) = make_float2(a, b);
        }
    }
    if (nodeB < N_NODES) {
        float* out = &g_x1[(size_t)nodeB * H_DIM];
#pragma unroll
        for (int j = 0; j < 25; j++) {
            float a, b; unpack2(accB[j], a, b);
            a = fmaxf(a + __ldg(&b1[2 * j]),     0.f);
            b = fmaxf(b + __ldg(&b1[2 * j + 1]), 0.f);
            *(float2*)(out + 2 * j) = make_float2(a, b);
        }
    }
}

// ---------------- K2: fused layers 2..4 -> z ------------------------------
__global__ __launch_bounds__(128) void mlp_tail_kernel(
    const float* __restrict__ W2, const float* __restrict__ b2,
    const float* __restrict__ W3, const float* __restrict__ b3,
    const float* __restrict__ W4, const float* __restrict__ b4)
{
    __shared__ __align__(16) float sW2[2500];
    __shared__ __align__(16) float sW3[2500];
    __shared__ __align__(16) float sW4[304];
    __shared__ float sB2[56], sB3[56], sB4[8];

    int tid = threadIdx.x;
    for (int i = tid; i < 2500; i += 128) { sW2[i] = W2[i]; sW3[i] = W3[i]; }
    for (int i = tid; i < 300;  i += 128) sW4[i] = W4[i];
    if (tid < 50) { sB2[tid] = b2[tid]; sB3[tid] = b3[tid]; }
    if (tid < 6)  sB4[tid] = b4[tid];
    __syncthreads();

    int node = blockIdx.x * 128 + tid;
    if (node >= N_NODES) return;

    float xa[50];
    const float* xin = &g_x1[(size_t)node * H_DIM];
#pragma unroll
    for (int j = 0; j < 25; j++) {
        float2 v = *(const float2*)(xin + 2 * j);
        xa[2 * j] = v.x; xa[2 * j + 1] = v.y;
    }

    // layer 2
    {
        ull acc[25];
#pragma unroll
        for (int j = 0; j < 25; j++) acc[j] = 0ull;
#pragma unroll
        for (int k = 0; k < 50; k++) {
            ull f2 = pack2(xa[k], xa[k]);
            const float* wr = &sW2[k * 50];
#pragma unroll
            for (int j = 0; j < 25; j++)
                acc[j] = ffma2(f2, *(const ull*)(wr + 2 * j), acc[j]);
        }
#pragma unroll
        for (int j = 0; j < 25; j++) {
            float a, b; unpack2(acc[j], a, b);
            xa[2 * j]     = fmaxf(a + sB2[2 * j],     0.f);
            xa[2 * j + 1] = fmaxf(b + sB2[2 * j + 1], 0.f);
        }
    }
    // layer 3
    {
        ull acc[25];
#pragma unroll
        for (int j = 0; j < 25; j++) acc[j] = 0ull;
#pragma unroll
        for (int k = 0; k < 50; k++) {
            ull f2 = pack2(xa[k], xa[k]);
            const float* wr = &sW3[k * 50];
#pragma unroll
            for (int j = 0; j < 25; j++)
                acc[j] = ffma2(f2, *(const ull*)(wr + 2 * j), acc[j]);
        }
#pragma unroll
        for (int j = 0; j < 25; j++) {
            float a, b; unpack2(acc[j], a, b);
            xa[2 * j]     = fmaxf(a + sB3[2 * j],     0.f);
            xa[2 * j + 1] = fmaxf(b + sB3[2 * j + 1], 0.f);
        }
    }
    // layer 4 -> z (padded row of 8)
    {
        ull acc[3] = {0ull, 0ull, 0ull};
#pragma unroll
        for (int k = 0; k < 50; k++) {
            ull f2 = pack2(xa[k], xa[k]);
            const float* wr = &sW4[k * 6];
#pragma unroll
            for (int j = 0; j < 3; j++)
                acc[j] = ffma2(f2, *(const ull*)(wr + 2 * j), acc[j]);
        }
        float zr[6];
#pragma unroll
        for (int j = 0; j < 3; j++) {
            float a, b; unpack2(acc[j], a, b);
            zr[2 * j]     = a + sB4[2 * j];
            zr[2 * j + 1] = b + sB4[2 * j + 1];
        }
        float* zp = &g_z[(size_t)node * 8];
        *(float4*)zp       = make_float4(zr[0], zr[1], zr[2], zr[3]);
        *(float2*)(zp + 4) = make_float2(zr[4], zr[5]);
        *(float2*)(zp + 6) = make_float2(0.f, 0.f);
    }
}

// ---------------- K3: per-layer exp tables (pads untouched, stay 0) -------
__global__ void table_kernel() {
    int n = blockIdx.x * 256 + threadIdx.x;
    if (n >= N_NODES) return;
    const float* zp = &g_z[(size_t)n * 8];
    float4 z4 = *(const float4*)zp;
    float2 z2 = *(const float2*)(zp + 4);
    float zz[6] = {z4.x, z4.y, z4.z, z4.w, z2.x, z2.y};
    float em[6], ep[6];
#pragma unroll
    for (int c = 0; c < 6; c++) { ep[c] = __expf(zz[c]); em[c] = __expf(-zz[c]); }
    float* e1 = &g_Em[(size_t)n * 8];
    float* e2 = &g_Ep[(size_t)n * 8];
    *(float4*)e1       = make_float4(em[0], em[1], em[2], em[3]);
    *(float2*)(e1 + 4) = make_float2(em[4], em[5]);
    *(float4*)e2       = make_float4(ep[0], ep[1], ep[2], ep[3]);
    *(float2*)(e2 + 4) = make_float2(ep[4], ep[5]);
}

// ---------------- K4: edge enhancement, pair-lane layout ------------------
// 2 threads per edge: even lane = classes 0-3, odd lane = classes 4-5 + pads.
// Every lane issues the same LDG.128 / RED.128; pair lanes share one 128B
// line -> gather wavefronts halved. Pad words add 0.0 (harmless).
__global__ __launch_bounds__(256) void edge_kernel(
    const int* __restrict__ sx, const int* __restrict__ sy,
    const float* __restrict__ cw)   // clause_weights + 6*layer
{
    int t = blockIdx.x * 256 + threadIdx.x;
    int e = t >> 1;
    if (e >= M_EDGES) return;
    int h = t & 1;                  // half: 0 -> classes 0-3, 1 -> classes 4,5,pad,pad
    int a = sx[e], b = sy[e];
    float v = g_Vexp[e];

    const float4 u = *(const float4*)(g_Em + (size_t)a * 8 + h * 4);
    const float4 w = *(const float4*)(g_Ep + (size_t)b * 8 + h * 4);

    // clause weights for this half; pad lanes get 0 (also avoids OOB read)
    float c0 = __ldg(cw + h * 4 + 0);
    float c1 = __ldg(cw + h * 4 + 1);
    float c2 = h ? 0.f : __ldg(cw + 2);
    float c3 = h ? 0.f : __ldg(cw + 3);

    float4 dx, dy;
    {
        float S = u.x + v + w.x; float tt = c0 * rcpa(S);
        dx.x = -tt * u.x; dy.x = tt * w.x;
    }
    {
        float S = u.y + v + w.y; float tt = c1 * rcpa(S);
        dx.y = -tt * u.y; dy.y = tt * w.y;
    }
    {
        float S = u.z + v + w.z; float tt = c2 * rcpa(S);
        dx.z = -tt * u.z; dy.z = tt * w.z;
    }
    {
        float S = u.w + v + w.w; float tt = c3 * rcpa(S);
        dx.w = -tt * u.w; dy.w = tt * w.w;
    }
    atomicAdd((float4*)(g_z + (size_t)a * 8 + h * 4), dx);
    atomicAdd((float4*)(g_z + (size_t)b * 8 + h * 4), dy);
}

// ---------------- K5: final softmax -> d_out ------------------------------
__global__ void softmax_kernel(float* __restrict__ out) {
    int n = blockIdx.x * 256 + threadIdx.x;
    if (n >= N_NODES) return;
    const float* zp = &g_z[(size_t)n * 8];
    float4 z4 = *(const float4*)zp;
    float2 z2 = *(const float2*)(zp + 4);
    float zz[6] = {z4.x, z4.y, z4.z, z4.w, z2.x, z2.y};
    float mx = zz[0];
#pragma unroll
    for (int c = 1; c < 6; c++) mx = fmaxf(mx, zz[c]);
    float e[6], s = 0.f;
#pragma unroll
    for (int c = 0; c < 6; c++) { e[c] = __expf(zz[c] - mx); s += e[c]; }
    float inv = rcpa(s);
    float* op = out + (size_t)n * 6;
#pragma unroll
    for (int c = 0; c < 6; c++) op[c] = e[c] * inv;
}

// ---------------- launcher ------------------------------------------------
extern "C" void kernel_launch(void* const* d_in, const int* in_sizes, int n_in,
                              void* d_out, int out_size)
{
    const float* F   = (const float*)d_in[0];
    const float* rel = (const float*)d_in[1];
    const int*   sx  = (const int*)d_in[2];
    const int*   sy  = (const int*)d_in[3];
    const float* W1  = (const float*)d_in[4];
    const float* b1  = (const float*)d_in[5];
    const float* W2  = (const float*)d_in[6];
    const float* b2  = (const float*)d_in[7];
    const float* W3  = (const float*)d_in[8];
    const float* b3  = (const float*)d_in[9];
    const float* W4  = (const float*)d_in[10];
    const float* b4  = (const float*)d_in[11];
    const float* cw  = (const float*)d_in[12];
    float* out = (float*)d_out;

    vexp_kernel    <<<(M_EDGES + 255) / 256, 256>>>(rel);           // launch 0
    gemm1_kernel   <<<(N_NODES + 255) / 256, 128>>>(F, W1, b1);     // launch 1
    mlp_tail_kernel<<<(N_NODES + 127) / 128, 128>>>(W2, b2, W3, b3, W4, b4); // 2

    for (int l = 0; l < L_LAYERS; l++) {
        table_kernel<<<(N_NODES + 255) / 256, 256>>>();             // 3, 6, 8
        if (l == 0) nop_kernel<<<1, 32>>>();                        // 4: aligns ncu -s 5
        edge_kernel <<<(2 * M_EDGES + 255) / 256, 256>>>(sx, sy, cw + l * 6); // 5 <- captured
    }
    softmax_kernel<<<(N_NODES + 255) / 256, 256>>>(out);
}